// round 1
// baseline (speedup 1.0000x reference)
#include <cuda_runtime.h>

#define N_ATOMS 1024
#define NSHIFT 27
#define CUT2 25.0f           // CUTOFF^2 = 5.0^2

#define ITILE 16             // i-rows per block
#define JTILE 64             // j-cols per block
#define BTHREADS 256
#define ROW_UNITS (JTILE * NSHIFT / 4)      // 432 units (of 4 pairs) per i-row
#define UNITS (ITILE * ROW_UNITS)           // 6912 = 256 * 27

// Scratch (static device globals — no allocation).
__device__ float4 g_B[N_ATOMS * NSHIFT];    // B[j][s] = cart[j] + shift_cart[s]
__device__ float4 g_cart[N_ATOMS];          // cart[i]

// Kernel 1: build cart + B table. 27648 threads, negligible time.
__global__ void build_B(const float* __restrict__ frac,
                        const float* __restrict__ cell) {
    int t = blockIdx.x * blockDim.x + threadIdx.x;
    if (t >= N_ATOMS * NSHIFT) return;
    int j = t / NSHIFT;
    int s = t - j * NSHIFT;

    float c[9];
#pragma unroll
    for (int m = 0; m < 9; m++) c[m] = __ldg(cell + m);

    float f0 = __ldg(frac + 3 * j + 0);
    float f1 = __ldg(frac + 3 * j + 1);
    float f2 = __ldg(frac + 3 * j + 2);

    // shift components in {-1,0,1}; S = a*9 + b*3 + c with comps (a-1, b-1, c-1)
    float sx = (float)(s / 9 - 1);
    float sy = (float)((s / 3) % 3 - 1);
    float sz = (float)(s % 3 - 1);

    float cart[3], sc[3];
#pragma unroll
    for (int k = 0; k < 3; k++) {
        // left-to-right fma chain: ((f0*c0 + f1*c1) + f2*c2)
        cart[k] = fmaf(f2, c[6 + k], fmaf(f1, c[3 + k], f0 * c[k]));
        sc[k]   = fmaf(sz, c[6 + k], fmaf(sy, c[3 + k], sx * c[k]));
    }

    // B = cart[j] + shift_cart[s]  (single add, same order as reference)
    g_B[t] = make_float4(__fadd_rn(cart[0], sc[0]),
                         __fadd_rn(cart[1], sc[1]),
                         __fadd_rn(cart[2], sc[2]), 0.0f);
    if (s == 0) g_cart[j] = make_float4(cart[0], cart[1], cart[2], 0.0f);
}

// Kernel 2: write masked_disp [1024,1024,27,3]. One block = 16 i-rows x 64 j-cols.
// Each thread-unit handles 4 consecutive (j,s) pairs = 12 floats = 3 x STG.128.
__global__ void __launch_bounds__(BTHREADS)
radius_out(float* __restrict__ out) {
    __shared__ float4 shB[JTILE * NSHIFT];   // 1728 float4 = 27 KB
    __shared__ float4 shC[ITILE];

    const int i0 = blockIdx.x * ITILE;
    const int j0 = blockIdx.y * JTILE;
    const int tid = threadIdx.x;

    // B tile is contiguous in g_B (j-major)
    for (int t = tid; t < JTILE * NSHIFT; t += BTHREADS)
        shB[t] = g_B[j0 * NSHIFT + t];
    if (tid < ITILE)
        shC[tid] = g_cart[i0 + tid];
    __syncthreads();

#pragma unroll 1
    for (int w = tid; w < UNITS; w += BTHREADS) {
        int il = w / ROW_UNITS;              // local i (0..15)
        int r  = w - il * ROW_UNITS;         // unit within row (0..431)
        int p  = r * 4;                      // first pair index: p = jl*27 + s
        int jl = p / 27;
        int s  = p - jl * 27;

        float4 ci = shC[il];

        float o[12];
#pragma unroll
        for (int q = 0; q < 4; q++) {
            float4 b = shB[jl * NSHIFT + s];
            float dx = __fadd_rn(b.x, -ci.x);
            float dy = __fadd_rn(b.y, -ci.y);
            float dz = __fadd_rn(b.z, -ci.z);
            // (dx*dx + dy*dy) + dz*dz, no contraction — matches reference
            float d2 = __fadd_rn(__fadd_rn(__fmul_rn(dx, dx), __fmul_rn(dy, dy)),
                                 __fmul_rn(dz, dz));
            bool keep = d2 < CUT2;           // self-edge gives disp==+0 anyway
            o[3 * q + 0] = keep ? dx : 0.0f;
            o[3 * q + 1] = keep ? dy : 0.0f;
            o[3 * q + 2] = keep ? dz : 0.0f;
            s++;
            if (s == NSHIFT) { s = 0; jl++; }
        }

        // Row base: ((i*1024 + j0) * 81); j0 % 4 == 0 so base is 16B-aligned,
        // and r*12 floats keeps 16B alignment.
        float* rowbase = out + (unsigned)((i0 + il) * N_ATOMS + j0) * 81u;
        float4* dst = (float4*)(rowbase + r * 12);
        __stcs(dst + 0, make_float4(o[0], o[1],  o[2],  o[3]));
        __stcs(dst + 1, make_float4(o[4], o[5],  o[6],  o[7]));
        __stcs(dst + 2, make_float4(o[8], o[9],  o[10], o[11]));
    }
}

extern "C" void kernel_launch(void* const* d_in, const int* in_sizes, int n_in,
                              void* d_out, int out_size) {
    const float* frac = (const float*)d_in[0];   // [1024,3]
    const float* cell = (const float*)d_in[1];   // [3,3]
    float* out = (float*)d_out;                  // [1024,1024,27,3]

    build_B<<<(N_ATOMS * NSHIFT + 255) / 256, 256>>>(frac, cell);
    dim3 grid(N_ATOMS / ITILE, N_ATOMS / JTILE); // (64, 16) = 1024 blocks
    radius_out<<<grid, BTHREADS>>>(out);
}

// round 2
// speedup vs baseline: 1.9272x; 1.9272x over previous
#include <cuda_runtime.h>

#define N_ATOMS 1024
#define NSHIFT 27
#define CUT2 25.0f                 // CUTOFF^2

#define ITILE 32                   // i-rows per block
#define JTILE 32                   // j-cols per block
#define BTHREADS 256
#define PAIRS_TILE (JTILE * NSHIFT)          // 864 pairs in tile
#define UNITS_PER_ROW (JTILE * NSHIFT * 3 / 4)  // 648 float4 units per i-row
#define UNITS (ITILE * UNITS_PER_ROW)           // 20736 units per block

// Scratch (static device globals — no allocation).
__device__ float4 g_B[N_ATOMS * NSHIFT];    // B[j][s] = cart[j] + shift_cart[s]
__device__ float4 g_cart[N_ATOMS];          // cart[i]

// Kernel 1: build cart + B table. Negligible time.
__global__ void build_B(const float* __restrict__ frac,
                        const float* __restrict__ cell) {
    int t = blockIdx.x * blockDim.x + threadIdx.x;
    if (t >= N_ATOMS * NSHIFT) return;
    int j = t / NSHIFT;
    int s = t - j * NSHIFT;

    float c[9];
#pragma unroll
    for (int m = 0; m < 9; m++) c[m] = __ldg(cell + m);

    float f0 = __ldg(frac + 3 * j + 0);
    float f1 = __ldg(frac + 3 * j + 1);
    float f2 = __ldg(frac + 3 * j + 2);

    float sx = (float)(s / 9 - 1);
    float sy = (float)((s / 3) % 3 - 1);
    float sz = (float)(s % 3 - 1);

    float cart[3], sc[3];
#pragma unroll
    for (int k = 0; k < 3; k++) {
        cart[k] = fmaf(f2, c[6 + k], fmaf(f1, c[3 + k], f0 * c[k]));
        sc[k]   = fmaf(sz, c[6 + k], fmaf(sy, c[3 + k], sx * c[k]));
    }

    g_B[t] = make_float4(__fadd_rn(cart[0], sc[0]),
                         __fadd_rn(cart[1], sc[1]),
                         __fadd_rn(cart[2], sc[2]), 0.0f);
    if (s == 0) g_cart[j] = make_float4(cart[0], cart[1], cart[2], 0.0f);
}

// Kernel 2: fully-coalesced stores. Each thread handles one float4 (16B) of
// output per iteration; consecutive lanes -> consecutive addresses. A 16B
// chunk spans pairs p = off/3 and p+1; compute both, select by off%3.
__global__ void __launch_bounds__(BTHREADS)
radius_out(float* __restrict__ out) {
    __shared__ float4 shB[PAIRS_TILE];       // 13.5 KB
    __shared__ float4 shC[ITILE];

    const int i0 = blockIdx.x * ITILE;
    const int j0 = blockIdx.y * JTILE;
    const int tid = threadIdx.x;

    for (int t = tid; t < PAIRS_TILE; t += BTHREADS)
        shB[t] = g_B[j0 * NSHIFT + t];
    if (tid < ITILE)
        shC[tid] = g_cart[i0 + tid];
    __syncthreads();

#pragma unroll 1
    for (int w = tid; w < UNITS; w += BTHREADS) {
        unsigned il = (unsigned)w / UNITS_PER_ROW;          // local i row
        unsigned u  = (unsigned)w - il * UNITS_PER_ROW;     // unit in row (0..647)
        unsigned off = u * 4u;                              // float offset in row seg
        unsigned pl = off / 3u;                             // first pair (0..862)
        unsigned c0 = off - pl * 3u;                        // component phase (0..2)

        float4 bA = shB[pl];
        float4 bB = shB[pl + 1];
        float4 ci = shC[il];

        // pair A
        float ax = __fadd_rn(bA.x, -ci.x);
        float ay = __fadd_rn(bA.y, -ci.y);
        float az = __fadd_rn(bA.z, -ci.z);
        float d2A = __fadd_rn(__fadd_rn(__fmul_rn(ax, ax), __fmul_rn(ay, ay)),
                              __fmul_rn(az, az));
        bool kA = d2A < CUT2;
        float a0 = kA ? ax : 0.0f;
        float a1 = kA ? ay : 0.0f;
        float a2 = kA ? az : 0.0f;

        // pair B
        float bx = __fadd_rn(bB.x, -ci.x);
        float by = __fadd_rn(bB.y, -ci.y);
        float bz = __fadd_rn(bB.z, -ci.z);
        float d2B = __fadd_rn(__fadd_rn(__fmul_rn(bx, bx), __fmul_rn(by, by)),
                              __fmul_rn(bz, bz));
        bool kB = d2B < CUT2;
        float a3 = kB ? bx : 0.0f;
        float a4 = kB ? by : 0.0f;
        float a5 = kB ? bz : 0.0f;

        // select window [c0, c0+3] out of {a0..a5}
        float o0 = (c0 == 0) ? a0 : ((c0 == 1) ? a1 : a2);
        float o1 = (c0 == 0) ? a1 : ((c0 == 1) ? a2 : a3);
        float o2 = (c0 == 0) ? a2 : ((c0 == 1) ? a3 : a4);
        float o3 = (c0 == 0) ? a3 : ((c0 == 1) ? a4 : a5);

        // global float index: ((i*1024 + j0)*81) + off  (16B-aligned: both
        // i*82944 and j0*2592... j0*81 with j0%32==0 -> j0*81 % 4 == 0)
        unsigned base = ((i0 + il) * (unsigned)N_ATOMS + (unsigned)j0) * 81u + off;
        __stcs((float4*)(out + base), make_float4(o0, o1, o2, o3));
    }
}

extern "C" void kernel_launch(void* const* d_in, const int* in_sizes, int n_in,
                              void* d_out, int out_size) {
    const float* frac = (const float*)d_in[0];   // [1024,3]
    const float* cell = (const float*)d_in[1];   // [3,3]
    float* out = (float*)d_out;                  // [1024,1024,27,3]

    build_B<<<(N_ATOMS * NSHIFT + 255) / 256, 256>>>(frac, cell);
    dim3 grid(N_ATOMS / ITILE, N_ATOMS / JTILE); // 32 x 32 = 1024 blocks
    radius_out<<<grid, BTHREADS>>>(out);
}